// round 6
// baseline (speedup 1.0000x reference)
#include <cuda_runtime.h>
#include <cuda_bf16.h>
#include <cstdint>

#define BB 8
#define SS 1024
#define DD 1024
#define HH 16
#define DH 64
#define KDIM 1024

// ---------------- scratch (__device__ globals; allocation-free rule) --------
__device__ __nv_bfloat16 g_qkvh[(size_t)8192 * 3072]; // qkv hi
__device__ __nv_bfloat16 g_qkvl[(size_t)8192 * 3072]; // qkv lo
__device__ __nv_bfloat16 g_wqkv_h[3072 * 1024];       // W_qkv^T hi [N][K]
__device__ __nv_bfloat16 g_wqkv_l[3072 * 1024];
__device__ __nv_bfloat16 g_wout_h[1024 * 1024];       // W_out^T hi
__device__ __nv_bfloat16 g_wout_l[1024 * 1024];
__device__ __nv_bfloat16 g_ah[(size_t)8192 * 1024];   // activation / attn-out hi
__device__ __nv_bfloat16 g_al[(size_t)8192 * 1024];   // activation / attn-out lo

// ---------------- helpers ---------------------------------------------------
__device__ __forceinline__ uint32_t smem_u32(const void* p) {
    uint32_t a;
    asm("{ .reg .u64 t; cvta.to.shared.u64 t, %1; cvt.u32.u64 %0, t; }"
        : "=r"(a) : "l"(p));
    return a;
}
#define LDSM_X4(r, addr)                                                        \
    asm volatile("ldmatrix.sync.aligned.m8n8.x4.shared.b16 {%0,%1,%2,%3}, [%4];"\
        : "=r"((r)[0]), "=r"((r)[1]), "=r"((r)[2]), "=r"((r)[3]) : "r"(addr))
#define LDSM_X4_T(r, addr)                                                      \
    asm volatile("ldmatrix.sync.aligned.m8n8.x4.trans.shared.b16 {%0,%1,%2,%3}, [%4];"\
        : "=r"((r)[0]), "=r"((r)[1]), "=r"((r)[2]), "=r"((r)[3]) : "r"(addr))
#define MMA16816(d, a, b0, b1)                                                  \
    asm volatile("mma.sync.aligned.m16n8k16.row.col.f32.bf16.bf16.f32 "         \
        "{%0,%1,%2,%3}, {%4,%5,%6,%7}, {%8,%9}, {%0,%1,%2,%3};"                 \
        : "+f"((d)[0]), "+f"((d)[1]), "+f"((d)[2]), "+f"((d)[3])                \
        : "r"((a)[0]), "r"((a)[1]), "r"((a)[2]), "r"((a)[3]), "r"(b0), "r"(b1))
#define CP_ASYNC16(sa, gp)                                                      \
    asm volatile("cp.async.cg.shared.global [%0], [%1], 16;"                    \
                 :: "r"(sa), "l"(gp) : "memory")
#define CP_COMMIT() asm volatile("cp.async.commit_group;" ::: "memory")
#define CP_WAIT0()  asm volatile("cp.async.wait_group 0;" ::: "memory")
#define CP_WAIT1()  asm volatile("cp.async.wait_group 1;" ::: "memory")
#define CP_WAIT2()  asm volatile("cp.async.wait_group 2;" ::: "memory")

__device__ __forceinline__ uint32_t pack_bf16(__nv_bfloat16 a, __nv_bfloat16 b) {
    return (uint32_t)__bfloat16_as_ushort(a) | ((uint32_t)__bfloat16_as_ushort(b) << 16);
}
__device__ __forceinline__ void split1(float v, __nv_bfloat16& h, __nv_bfloat16& l) {
    h = __float2bfloat16(v);
    float hf = __uint_as_float(((uint32_t)__bfloat16_as_ushort(h)) << 16);
    l = __float2bfloat16(v - hf);
}
__device__ __forceinline__ void split2(float a, float b, uint32_t& h, uint32_t& l) {
    __nv_bfloat16 ha, la, hb, lb;
    split1(a, ha, la); split1(b, hb, lb);
    h = pack_bf16(ha, hb); l = pack_bf16(la, lb);
}
__device__ __forceinline__ float ex2(float x) {
    float r;
    asm("ex2.approx.f32 %0, %1;" : "=f"(r) : "f"(x));
    return r;
}

// ---------------------------------------------------------------------------
// Weight pre-pass: W[K,N] fp32 -> H,L [N,K] bf16 (transpose + hi/lo split)
// ---------------------------------------------------------------------------
__global__ void __launch_bounds__(256)
wsplit_kernel(const float* __restrict__ W, __nv_bfloat16* __restrict__ H,
              __nv_bfloat16* __restrict__ L, int K, int N) {
    __shared__ float t[32][33];
    const int tx = threadIdx.x, ty = threadIdx.y;
    const int n0 = blockIdx.x * 32, k0 = blockIdx.y * 32;
#pragma unroll
    for (int i = 0; i < 32; i += 8)
        t[ty + i][tx] = W[(size_t)(k0 + ty + i) * N + n0 + tx];
    __syncthreads();
#pragma unroll
    for (int i = 0; i < 32; i += 8) {
        const int n = ty + i;
        float v = t[tx][n];
        __nv_bfloat16 h, l;
        split1(v, h, l);
        H[(size_t)(n0 + n) * K + k0 + tx] = h;
        L[(size_t)(n0 + n) * K + k0 + tx] = l;
    }
}

// ---------------------------------------------------------------------------
// Activation split: X fp32 [M][K] -> H,L bf16 same layout (elementwise)
// ---------------------------------------------------------------------------
__global__ void __launch_bounds__(256)
xsplit_kernel(const float* __restrict__ X, __nv_bfloat16* __restrict__ H,
              __nv_bfloat16* __restrict__ L) {
    const size_t i4 = (size_t)blockIdx.x * 256 + threadIdx.x;
    float4 v = *(const float4*)(X + i4 * 4);
    __nv_bfloat16 h0, h1, h2, h3, l0, l1, l2, l3;
    split1(v.x, h0, l0); split1(v.y, h1, l1);
    split1(v.z, h2, l2); split1(v.w, h3, l3);
    *(uint2*)(H + i4 * 4) = make_uint2(pack_bf16(h0, h1), pack_bf16(h2, h3));
    *(uint2*)(L + i4 * 4) = make_uint2(pack_bf16(l0, l1), pack_bf16(l2, l3));
}

// ---------------------------------------------------------------------------
// HMMA GEMM: 512 threads, 16 warps (4x4), warp tile 32x32, CTA tile 128x128.
// KC=64, 3-stage cp.async pipeline. SPLITOUT: write bf16 hi/lo.
// ---------------------------------------------------------------------------
#define KC 64
#define RSTRIDE 144
#define ARR 18432
#define OFF_AH 0
#define OFF_AL 18432
#define OFF_BH 36864
#define OFF_BL 55296
#define STAGE 73728
#define NSTAGE 3
#define GEMM_SMEM (NSTAGE * STAGE)
#define NCHUNK 16

template <bool SPLITOUT>
__global__ void __launch_bounds__(512, 1)
gemm_mma(const __nv_bfloat16* __restrict__ Ah, const __nv_bfloat16* __restrict__ Al,
         const __nv_bfloat16* __restrict__ Wh, const __nv_bfloat16* __restrict__ Wl,
         float* __restrict__ C, __nv_bfloat16* __restrict__ Ch,
         __nv_bfloat16* __restrict__ Cl, int N) {
    extern __shared__ char smem[];
    const uint32_t sb = smem_u32(smem);
    const int tid = threadIdx.x;
    const int warp = tid >> 5, lane = tid & 31;
    const int m0 = blockIdx.y * 128, n0 = blockIdx.x * 128;
    const int wm = (warp >> 2) * 32;          // 0/32/64/96
    const int wn = (warp & 3) * 32;           // 0/32/64/96

    float acc[2][4][4];
#pragma unroll
    for (int mt = 0; mt < 2; mt++)
#pragma unroll
        for (int nt = 0; nt < 4; nt++)
#pragma unroll
            for (int i = 0; i < 4; i++) acc[mt][nt][i] = 0.f;

    auto issue_stage = [&](int s) {
        const uint32_t so = sb + (uint32_t)(s % NSTAGE) * STAGE;
        const int k0 = s * KC;
#pragma unroll
        for (int i = 0; i < 2; i++) {
            const int idx = tid + i * 512;     // 0..1023
            const int row = idx >> 3;
            const int k8 = (idx & 7) * 8;
            const uint32_t soff = so + (uint32_t)row * RSTRIDE + (uint32_t)k8 * 2;
            const size_t ga = (size_t)(m0 + row) * KDIM + k0 + k8;
            const size_t gb = (size_t)(n0 + row) * KDIM + k0 + k8;
            CP_ASYNC16(soff + OFF_AH, Ah + ga);
            CP_ASYNC16(soff + OFF_AL, Al + ga);
            CP_ASYNC16(soff + OFF_BH, Wh + gb);
            CP_ASYNC16(soff + OFF_BL, Wl + gb);
        }
    };

    issue_stage(0); CP_COMMIT();
    issue_stage(1); CP_COMMIT();

#pragma unroll 1
    for (int c = 0; c < NCHUNK; c++) {
        if (c + 2 < NCHUNK) issue_stage(c + 2);
        CP_COMMIT();
        CP_WAIT2();
        __syncthreads();

        const uint32_t cur = (uint32_t)(c % NSTAGE) * STAGE;
        const uint32_t abase = sb + cur + (uint32_t)(wm + (lane & 15)) * RSTRIDE
                             + (uint32_t)(lane >> 4) * 16;
        const uint32_t bbase = sb + cur + OFF_BH + (uint32_t)(wn + (lane & 7)) * RSTRIDE
                             + (uint32_t)(lane >> 3) * 16;
#pragma unroll
        for (int s2 = 0; s2 < 2; s2++) {
            uint32_t bh[4][4], bl[4][4];
#pragma unroll
            for (int nt = 0; nt < 4; nt++) {
                const uint32_t ba = bbase + nt * 8 * RSTRIDE + s2 * 64;
                LDSM_X4(bh[nt], ba);
                LDSM_X4(bl[nt], ba + ARR);
            }
#pragma unroll
            for (int s = 0; s < 2; s++) {
                uint32_t ahr[2][4], alr[2][4];
#pragma unroll
                for (int mt = 0; mt < 2; mt++) {
                    const uint32_t aa = abase + mt * 16 * RSTRIDE + (s2 * 2 + s) * 32;
                    LDSM_X4(ahr[mt], aa);
                    LDSM_X4(alr[mt], aa + ARR);
                }
#pragma unroll
                for (int mt = 0; mt < 2; mt++)
#pragma unroll
                    for (int nt = 0; nt < 4; nt++) {
                        MMA16816(acc[mt][nt], ahr[mt], bh[nt][2 * s], bh[nt][2 * s + 1]);
                        MMA16816(acc[mt][nt], ahr[mt], bl[nt][2 * s], bl[nt][2 * s + 1]);
                        MMA16816(acc[mt][nt], alr[mt], bh[nt][2 * s], bh[nt][2 * s + 1]);
                    }
            }
        }
        __syncthreads();
    }

#pragma unroll
    for (int mt = 0; mt < 2; mt++) {
        const int row = m0 + wm + mt * 16 + (lane >> 2);
#pragma unroll
        for (int nt = 0; nt < 4; nt++) {
            const int col = n0 + wn + nt * 8 + (lane & 3) * 2;
            if (SPLITOUT) {
                uint32_t h01, l01, h23, l23;
                split2(acc[mt][nt][0], acc[mt][nt][1], h01, l01);
                split2(acc[mt][nt][2], acc[mt][nt][3], h23, l23);
                *(uint32_t*)(Ch + (size_t)row * N + col) = h01;
                *(uint32_t*)(Cl + (size_t)row * N + col) = l01;
                *(uint32_t*)(Ch + (size_t)(row + 8) * N + col) = h23;
                *(uint32_t*)(Cl + (size_t)(row + 8) * N + col) = l23;
            } else {
                *(float2*)(C + (size_t)row * N + col) =
                    make_float2(acc[mt][nt][0], acc[mt][nt][1]);
                *(float2*)(C + (size_t)(row + 8) * N + col) =
                    make_float2(acc[mt][nt][2], acc[mt][nt][3]);
            }
        }
    }
}

// ---------------------------------------------------------------------------
// HMMA causal flash attention (unchanged from R5).
// ---------------------------------------------------------------------------
#define A_OFF_QH 0
#define A_OFF_QL 18432
#define A_KV0 36864
#define A_KVSTAGE 36864          // Kh(9216) Kl(9216) Vh(9216) Vl(9216)
#define ATT_SMEM (A_KV0 + 3 * A_KVSTAGE)

__global__ void __launch_bounds__(256, 1)
attn_mma(const __nv_bfloat16* __restrict__ qkvh, const __nv_bfloat16* __restrict__ qkvl,
         __nv_bfloat16* __restrict__ Oh, __nv_bfloat16* __restrict__ Ol) {
    extern __shared__ char smem[];
    const uint32_t sb = smem_u32(smem);
    const int tid = threadIdx.x;
    const int warp = tid >> 5, lane = tid & 31;
    const int qt = 7 - blockIdx.x;
    const int b = blockIdx.y >> 4, h = blockIdx.y & 15;
    const int qrow0 = qt * 128;
    const size_t rowbase = (size_t)b * SS;
    const int jlast = 2 * qt + 1;

#pragma unroll
    for (int i = 0; i < 4; i++) {
        const int idx = tid + i * 256;
        const int row = idx >> 3;
        const int c8 = (idx & 7) * 8;
        const size_t g = (rowbase + qrow0 + row) * 3072 + h * DH + c8;
        const uint32_t so = sb + (uint32_t)row * RSTRIDE + (uint32_t)c8 * 2;
        CP_ASYNC16(so + A_OFF_QH, qkvh + g);
        CP_ASYNC16(so + A_OFF_QL, qkvl + g);
    }
    auto issue_kv = [&](int j) {
        const uint32_t so = sb + A_KV0 + (uint32_t)(j % 3) * A_KVSTAGE;
#pragma unroll
        for (int i = 0; i < 2; i++) {
            const int idx = tid + i * 256;
            const int row = idx >> 3;
            const int c8 = (idx & 7) * 8;
            const size_t g = (rowbase + j * 64 + row) * 3072 + h * DH + c8;
            const uint32_t soff = so + (uint32_t)row * RSTRIDE + (uint32_t)c8 * 2;
            CP_ASYNC16(soff,         qkvh + g + 1024);
            CP_ASYNC16(soff + 9216,  qkvl + g + 1024);
            CP_ASYNC16(soff + 18432, qkvh + g + 2048);
            CP_ASYNC16(soff + 27648, qkvl + g + 2048);
        }
    };
    issue_kv(0); CP_COMMIT();
    if (jlast >= 1) { issue_kv(1); CP_COMMIT(); }

    if (jlast >= 1) { CP_WAIT1(); } else { CP_WAIT0(); }
    __syncthreads();

    uint32_t qh[4][4], ql[4][4];
    {
        const uint32_t qbase = sb + (uint32_t)(warp * 16 + (lane & 15)) * RSTRIDE
                             + (uint32_t)(lane >> 4) * 16;
#pragma unroll
        for (int ks = 0; ks < 4; ks++) {
            LDSM_X4(qh[ks], qbase + A_OFF_QH + ks * 32);
            LDSM_X4(ql[ks], qbase + A_OFF_QL + ks * 32);
        }
    }

    float O[8][4];
#pragma unroll
    for (int dt = 0; dt < 8; dt++)
#pragma unroll
        for (int i = 0; i < 4; i++) O[dt][i] = 0.f;
    float m0 = -1e30f, m1 = -1e30f, l0 = 0.f, l1 = 0.f;

    const int rg0 = qrow0 + warp * 16 + (lane >> 2);
    const float SC = 0.18033688011112042f;     // (1/8) * log2(e)

#pragma unroll 1
    for (int j = 0; j <= jlast; j++) {
        if (j + 2 <= jlast) { issue_kv(j + 2); CP_COMMIT(); }
        if (j + 2 <= jlast)      { CP_WAIT2(); }
        else if (j + 1 <= jlast) { CP_WAIT1(); }
        else                     { CP_WAIT0(); }
        __syncthreads();

        const bool active = (64 * j) <= (qrow0 + warp * 16 + 15);
        if (active) {
            const uint32_t so = sb + A_KV0 + (uint32_t)(j % 3) * A_KVSTAGE;

            float S[8][4];
#pragma unroll
            for (int nt = 0; nt < 8; nt++)
#pragma unroll
                for (int i = 0; i < 4; i++) S[nt][i] = 0.f;

            const uint32_t kbase = so + (uint32_t)(lane & 7) * RSTRIDE
                                 + (uint32_t)(lane >> 3) * 16;
#pragma unroll
            for (int nt = 0; nt < 8; nt++) {
                const uint32_t ka = kbase + nt * 8 * RSTRIDE;
                uint32_t kh0[4], kh1[4], kl0[4], kl1[4];
                LDSM_X4(kh0, ka);          LDSM_X4(kh1, ka + 64);
                LDSM_X4(kl0, ka + 9216);   LDSM_X4(kl1, ka + 9216 + 64);
                MMA16816(S[nt], qh[0], kh0[0], kh0[1]);
                MMA16816(S[nt], qh[0], kl0[0], kl0[1]);
                MMA16816(S[nt], ql[0], kh0[0], kh0[1]);
                MMA16816(S[nt], qh[1], kh0[2], kh0[3]);
                MMA16816(S[nt], qh[1], kl0[2], kl0[3]);
                MMA16816(S[nt], ql[1], kh0[2], kh0[3]);
                MMA16816(S[nt], qh[2], kh1[0], kh1[1]);
                MMA16816(S[nt], qh[2], kl1[0], kl1[1]);
                MMA16816(S[nt], ql[2], kh1[0], kh1[1]);
                MMA16816(S[nt], qh[3], kh1[2], kh1[3]);
                MMA16816(S[nt], qh[3], kl1[2], kl1[3]);
                MMA16816(S[nt], ql[3], kh1[2], kh1[3]);
            }

            const bool needmask = (j >= 2 * qt);
            float mx0 = -1e30f, mx1 = -1e30f;
#pragma unroll
            for (int nt = 0; nt < 8; nt++) {
                float t0 = S[nt][0] * SC, t1 = S[nt][1] * SC;
                float t2 = S[nt][2] * SC, t3 = S[nt][3] * SC;
                if (needmask) {
                    const int col = 64 * j + 8 * nt + 2 * (lane & 3);
                    if (col > rg0)         t0 = -1e30f;
                    if (col + 1 > rg0)     t1 = -1e30f;
                    if (col > rg0 + 8)     t2 = -1e30f;
                    if (col + 1 > rg0 + 8) t3 = -1e30f;
                }
                S[nt][0] = t0; S[nt][1] = t1; S[nt][2] = t2; S[nt][3] = t3;
                mx0 = fmaxf(mx0, fmaxf(t0, t1));
                mx1 = fmaxf(mx1, fmaxf(t2, t3));
            }
            mx0 = fmaxf(mx0, __shfl_xor_sync(0xffffffffu, mx0, 1));
            mx0 = fmaxf(mx0, __shfl_xor_sync(0xffffffffu, mx0, 2));
            mx1 = fmaxf(mx1, __shfl_xor_sync(0xffffffffu, mx1, 1));
            mx1 = fmaxf(mx1, __shfl_xor_sync(0xffffffffu, mx1, 2));

            const float mn0 = fmaxf(m0, mx0), mn1 = fmaxf(m1, mx1);
            const float cr0 = ex2(m0 - mn0), cr1 = ex2(m1 - mn1);
            m0 = mn0; m1 = mn1;

            float ls0 = 0.f, ls1 = 0.f;
#pragma unroll
            for (int nt = 0; nt < 8; nt++) {
                const float p0 = ex2(S[nt][0] - m0), p1 = ex2(S[nt][1] - m0);
                const float p2 = ex2(S[nt][2] - m1), p3 = ex2(S[nt][3] - m1);
                S[nt][0] = p0; S[nt][1] = p1; S[nt][2] = p2; S[nt][3] = p3;
                ls0 += p0 + p1;
                ls1 += p2 + p3;
            }
            ls0 += __shfl_xor_sync(0xffffffffu, ls0, 1);
            ls0 += __shfl_xor_sync(0xffffffffu, ls0, 2);
            ls1 += __shfl_xor_sync(0xffffffffu, ls1, 1);
            ls1 += __shfl_xor_sync(0xffffffffu, ls1, 2);
            l0 = l0 * cr0 + ls0;
            l1 = l1 * cr1 + ls1;

#pragma unroll
            for (int dt = 0; dt < 8; dt++) {
                O[dt][0] *= cr0; O[dt][1] *= cr0;
                O[dt][2] *= cr1; O[dt][3] *= cr1;
            }

            uint32_t ph[4][4], pl[4][4];
#pragma unroll
            for (int ks = 0; ks < 4; ks++) {
                split2(S[2 * ks][0],     S[2 * ks][1],     ph[ks][0], pl[ks][0]);
                split2(S[2 * ks][2],     S[2 * ks][3],     ph[ks][1], pl[ks][1]);
                split2(S[2 * ks + 1][0], S[2 * ks + 1][1], ph[ks][2], pl[ks][2]);
                split2(S[2 * ks + 1][2], S[2 * ks + 1][3], ph[ks][3], pl[ks][3]);
            }

            const uint32_t vbase = so + 18432 + (uint32_t)lane * RSTRIDE;
#pragma unroll
            for (int dt = 0; dt < 8; dt++) {
                const uint32_t va = vbase + dt * 16;
                uint32_t vh0[4], vh1[4], vl0[4], vl1[4];
                LDSM_X4_T(vh0, va);                 LDSM_X4_T(vh1, va + 32 * RSTRIDE);
                LDSM_X4_T(vl0, va + 9216);          LDSM_X4_T(vl1, va + 9216 + 32 * RSTRIDE);
                MMA16816(O[dt], ph[0], vh0[0], vh0[1]);
                MMA16816(O[dt], ph[0], vl0[0], vl0[1]);
                MMA16816(O[dt], pl[0], vh0[0], vh0[1]);
                MMA16816(O[dt], ph[1], vh0[2], vh0[3]);
                MMA16816(O[dt], ph[1], vl0[2], vl0[3]);
                MMA16816(O[dt], pl[1], vh0[2], vh0[3]);
                MMA16816(O[dt], ph[2], vh1[0], vh1[1]);
                MMA16816(O[dt], ph[2], vl1[0], vl1[1]);
                MMA16816(O[dt], pl[2], vh1[0], vh1[1]);
                MMA16816(O[dt], ph[3], vh1[2], vh1[3]);
                MMA16816(O[dt], ph[3], vl1[2], vl1[3]);
                MMA16816(O[dt], pl[3], vh1[2], vh1[3]);
            }
        }
        __syncthreads();
    }

    const float inv0 = 1.f / l0, inv1 = 1.f / l1;
    const size_t row0 = rowbase + qrow0 + warp * 16 + (lane >> 2);
    const size_t row1 = row0 + 8;
#pragma unroll
    for (int dt = 0; dt < 8; dt++) {
        const int col = h * DH + dt * 8 + 2 * (lane & 3);
        uint32_t h01, l01, h23, l23;
        split2(O[dt][0] * inv0, O[dt][1] * inv0, h01, l01);
        split2(O[dt][2] * inv1, O[dt][3] * inv1, h23, l23);
        *(uint32_t*)(Oh + row0 * DD + col) = h01;
        *(uint32_t*)(Ol + row0 * DD + col) = l01;
        *(uint32_t*)(Oh + row1 * DD + col) = h23;
        *(uint32_t*)(Ol + row1 * DD + col) = l23;
    }
}

// ---------------------------------------------------------------------------
extern "C" void kernel_launch(void* const* d_in, const int* in_sizes, int n_in,
                              void* d_out, int out_size) {
    const float* x     = (const float*)d_in[0];   // [8,1024,1024]
    const float* w_qkv = (const float*)d_in[2];   // [1024,3072]
    const float* w_out = (const float*)d_in[3];   // [1024,1024]
    float* out = (float*)d_out;

    __nv_bfloat16 *wqh, *wql, *woh, *wol, *ah, *al, *qkvh, *qkvl;
    cudaGetSymbolAddress((void**)&wqh, g_wqkv_h);
    cudaGetSymbolAddress((void**)&wql, g_wqkv_l);
    cudaGetSymbolAddress((void**)&woh, g_wout_h);
    cudaGetSymbolAddress((void**)&wol, g_wout_l);
    cudaGetSymbolAddress((void**)&ah, g_ah);
    cudaGetSymbolAddress((void**)&al, g_al);
    cudaGetSymbolAddress((void**)&qkvh, g_qkvh);
    cudaGetSymbolAddress((void**)&qkvl, g_qkvl);

    cudaFuncSetAttribute(gemm_mma<true>,  cudaFuncAttributeMaxDynamicSharedMemorySize, GEMM_SMEM);
    cudaFuncSetAttribute(gemm_mma<false>, cudaFuncAttributeMaxDynamicSharedMemorySize, GEMM_SMEM);
    cudaFuncSetAttribute(attn_mma, cudaFuncAttributeMaxDynamicSharedMemorySize, ATT_SMEM);

    // 0) weight transpose+split, activation split
    wsplit_kernel<<<dim3(3072 / 32, 1024 / 32), dim3(32, 8)>>>(w_qkv, wqh, wql, 1024, 3072);
    wsplit_kernel<<<dim3(1024 / 32, 1024 / 32), dim3(32, 8)>>>(w_out, woh, wol, 1024, 1024);
    xsplit_kernel<<<(8192 * 1024 / 4) / 256, 256>>>(x, ah, al);

    // 1) QKV projection -> split bf16 qkv
    gemm_mma<true><<<dim3(3072 / 128, 8192 / 128), 512, GEMM_SMEM>>>(
        ah, al, wqh, wql, nullptr, qkvh, qkvl, 3072);

    // 2) causal flash attention (HMMA) -> split bf16 O
    attn_mma<<<dim3(8, BB * HH), 256, ATT_SMEM>>>(qkvh, qkvl, ah, al);

    // 3) output projection -> fp32 out
    gemm_mma<false><<<dim3(1024 / 128, 8192 / 128), 512, GEMM_SMEM>>>(
        ah, al, woh, wol, out, nullptr, nullptr, 1024);
}

// round 7
// speedup vs baseline: 1.1135x; 1.1135x over previous
#include <cuda_runtime.h>
#include <cuda_bf16.h>
#include <cstdint>

#define BB 8
#define SS 1024
#define DD 1024
#define HH 16
#define DH 64
#define KDIM 1024

// ---------------- scratch (__device__ globals; allocation-free rule) --------
__device__ __nv_bfloat16 g_qkvh[(size_t)8192 * 3072]; // qkv hi
__device__ __nv_bfloat16 g_qkvl[(size_t)8192 * 3072]; // qkv lo
__device__ __nv_bfloat16 g_wqkv_h[3072 * 1024];       // W_qkv^T hi [N][K]
__device__ __nv_bfloat16 g_wqkv_l[3072 * 1024];
__device__ __nv_bfloat16 g_wout_h[1024 * 1024];       // W_out^T hi
__device__ __nv_bfloat16 g_wout_l[1024 * 1024];
__device__ __nv_bfloat16 g_ah[(size_t)8192 * 1024];   // activation / attn-out hi
__device__ __nv_bfloat16 g_al[(size_t)8192 * 1024];   // activation / attn-out lo

// ---------------- helpers ---------------------------------------------------
__device__ __forceinline__ uint32_t smem_u32(const void* p) {
    uint32_t a;
    asm("{ .reg .u64 t; cvta.to.shared.u64 t, %1; cvt.u32.u64 %0, t; }"
        : "=r"(a) : "l"(p));
    return a;
}
#define LDSM_X4(r, addr)                                                        \
    asm volatile("ldmatrix.sync.aligned.m8n8.x4.shared.b16 {%0,%1,%2,%3}, [%4];"\
        : "=r"((r)[0]), "=r"((r)[1]), "=r"((r)[2]), "=r"((r)[3]) : "r"(addr))
#define LDSM_X2(r, addr)                                                        \
    asm volatile("ldmatrix.sync.aligned.m8n8.x2.shared.b16 {%0,%1}, [%2];"      \
        : "=r"((r)[0]), "=r"((r)[1]) : "r"(addr))
#define LDSM_X4_T(r, addr)                                                      \
    asm volatile("ldmatrix.sync.aligned.m8n8.x4.trans.shared.b16 {%0,%1,%2,%3}, [%4];"\
        : "=r"((r)[0]), "=r"((r)[1]), "=r"((r)[2]), "=r"((r)[3]) : "r"(addr))
#define MMA16816(d, a, b0, b1)                                                  \
    asm volatile("mma.sync.aligned.m16n8k16.row.col.f32.bf16.bf16.f32 "         \
        "{%0,%1,%2,%3}, {%4,%5,%6,%7}, {%8,%9}, {%0,%1,%2,%3};"                 \
        : "+f"((d)[0]), "+f"((d)[1]), "+f"((d)[2]), "+f"((d)[3])                \
        : "r"((a)[0]), "r"((a)[1]), "r"((a)[2]), "r"((a)[3]), "r"(b0), "r"(b1))
#define CP_ASYNC16(sa, gp)                                                      \
    asm volatile("cp.async.cg.shared.global [%0], [%1], 16;"                    \
                 :: "r"(sa), "l"(gp) : "memory")
#define CP_COMMIT() asm volatile("cp.async.commit_group;" ::: "memory")
#define CP_WAIT0()  asm volatile("cp.async.wait_group 0;" ::: "memory")
#define CP_WAIT1()  asm volatile("cp.async.wait_group 1;" ::: "memory")
#define CP_WAIT2()  asm volatile("cp.async.wait_group 2;" ::: "memory")

__device__ __forceinline__ uint32_t pack_bf16(__nv_bfloat16 a, __nv_bfloat16 b) {
    return (uint32_t)__bfloat16_as_ushort(a) | ((uint32_t)__bfloat16_as_ushort(b) << 16);
}
__device__ __forceinline__ void split1(float v, __nv_bfloat16& h, __nv_bfloat16& l) {
    h = __float2bfloat16(v);
    float hf = __uint_as_float(((uint32_t)__bfloat16_as_ushort(h)) << 16);
    l = __float2bfloat16(v - hf);
}
__device__ __forceinline__ void split2(float a, float b, uint32_t& h, uint32_t& l) {
    __nv_bfloat16 ha, la, hb, lb;
    split1(a, ha, la); split1(b, hb, lb);
    h = pack_bf16(ha, hb); l = pack_bf16(la, lb);
}
__device__ __forceinline__ float ex2(float x) {
    float r;
    asm("ex2.approx.f32 %0, %1;" : "=f"(r) : "f"(x));
    return r;
}

// ---------------------------------------------------------------------------
// Weight pre-pass: W[K,N] fp32 -> H,L [N,K] bf16 (transpose + hi/lo split)
// ---------------------------------------------------------------------------
__global__ void __launch_bounds__(256)
wsplit_kernel(const float* __restrict__ W, __nv_bfloat16* __restrict__ H,
              __nv_bfloat16* __restrict__ L, int K, int N) {
    __shared__ float t[32][33];
    const int tx = threadIdx.x, ty = threadIdx.y;
    const int n0 = blockIdx.x * 32, k0 = blockIdx.y * 32;
#pragma unroll
    for (int i = 0; i < 32; i += 8)
        t[ty + i][tx] = W[(size_t)(k0 + ty + i) * N + n0 + tx];
    __syncthreads();
#pragma unroll
    for (int i = 0; i < 32; i += 8) {
        const int n = ty + i;
        float v = t[tx][n];
        __nv_bfloat16 h, l;
        split1(v, h, l);
        H[(size_t)(n0 + n) * K + k0 + tx] = h;
        L[(size_t)(n0 + n) * K + k0 + tx] = l;
    }
}

// ---------------------------------------------------------------------------
// Activation split: X fp32 [M][K] -> H,L bf16 same layout (elementwise)
// ---------------------------------------------------------------------------
__global__ void __launch_bounds__(256)
xsplit_kernel(const float* __restrict__ X, __nv_bfloat16* __restrict__ H,
              __nv_bfloat16* __restrict__ L) {
    const size_t i4 = (size_t)blockIdx.x * 256 + threadIdx.x;
    float4 v = *(const float4*)(X + i4 * 4);
    __nv_bfloat16 h0, h1, h2, h3, l0, l1, l2, l3;
    split1(v.x, h0, l0); split1(v.y, h1, l1);
    split1(v.z, h2, l2); split1(v.w, h3, l3);
    *(uint2*)(H + i4 * 4) = make_uint2(pack_bf16(h0, h1), pack_bf16(h2, h3));
    *(uint2*)(L + i4 * 4) = make_uint2(pack_bf16(l0, l1), pack_bf16(l2, l3));
}

// ---------------------------------------------------------------------------
// HMMA GEMM: 256 threads, 8 warps (2x4), warp tile 64x64, CTA tile 128x256.
// KC=64, 2-stage cp.async pipeline. SPLITOUT: write bf16 hi/lo.
// Stage layout: Ah(18432) Al(18432) Bh(36864) Bl(36864) = 110592 B.
// ---------------------------------------------------------------------------
#define KC 64
#define RSTRIDE 144
#define OFF_AH 0
#define OFF_AL 18432
#define OFF_BH 36864
#define OFF_BL 73728
#define STAGE 110592
#define GEMM_SMEM (2 * STAGE)
#define NCHUNK 16

template <bool SPLITOUT>
__global__ void __launch_bounds__(256, 1)
gemm_mma(const __nv_bfloat16* __restrict__ Ah, const __nv_bfloat16* __restrict__ Al,
         const __nv_bfloat16* __restrict__ Wh, const __nv_bfloat16* __restrict__ Wl,
         float* __restrict__ C, __nv_bfloat16* __restrict__ Ch,
         __nv_bfloat16* __restrict__ Cl, int N) {
    extern __shared__ char smem[];
    const uint32_t sb = smem_u32(smem);
    const int tid = threadIdx.x;
    const int warp = tid >> 5, lane = tid & 31;
    const int m0 = blockIdx.y * 128, n0 = blockIdx.x * 256;
    const int wm = (warp >> 2) * 64;          // 0/64
    const int wn = (warp & 3) * 64;           // 0/64/128/192

    float acc[4][8][4];
#pragma unroll
    for (int mt = 0; mt < 4; mt++)
#pragma unroll
        for (int nt = 0; nt < 8; nt++)
#pragma unroll
            for (int i = 0; i < 4; i++) acc[mt][nt][i] = 0.f;

    auto issue_stage = [&](int s) {
        const uint32_t so = sb + (uint32_t)(s & 1) * STAGE;
        const int k0 = s * KC;
        // A hi/lo: 128 rows x 8 x 16B
#pragma unroll
        for (int i = 0; i < 4; i++) {
            const int idx = tid + i * 256;     // 0..1023
            const int row = idx >> 3;
            const int k8 = (idx & 7) * 8;
            const uint32_t soff = so + (uint32_t)row * RSTRIDE + (uint32_t)k8 * 2;
            const size_t ga = (size_t)(m0 + row) * KDIM + k0 + k8;
            CP_ASYNC16(soff + OFF_AH, Ah + ga);
            CP_ASYNC16(soff + OFF_AL, Al + ga);
        }
        // B hi/lo: 256 rows x 8 x 16B
#pragma unroll
        for (int i = 0; i < 8; i++) {
            const int idx = tid + i * 256;     // 0..2047
            const int row = idx >> 3;
            const int k8 = (idx & 7) * 8;
            const uint32_t soff = so + OFF_BH + (uint32_t)row * RSTRIDE + (uint32_t)k8 * 2;
            const size_t gb = (size_t)(n0 + row) * KDIM + k0 + k8;
            CP_ASYNC16(soff, Wh + gb);
            CP_ASYNC16(soff + (OFF_BL - OFF_BH), Wl + gb);
        }
    };

    issue_stage(0); CP_COMMIT();
    issue_stage(1); CP_COMMIT();

#pragma unroll 1
    for (int c = 0; c < NCHUNK; c++) {
        if (c == NCHUNK - 1) { CP_WAIT0(); } else { CP_WAIT1(); }
        __syncthreads();

        const uint32_t cur = (uint32_t)(c & 1) * STAGE;
        const uint32_t abase = sb + cur + (uint32_t)(wm + (lane & 15)) * RSTRIDE
                             + (uint32_t)(lane >> 4) * 16;
        const uint32_t bbase = sb + cur + OFF_BH + (uint32_t)(wn + (lane & 7)) * RSTRIDE
                             + (uint32_t)((lane >> 3) & 1) * 16;
#pragma unroll
        for (int k16 = 0; k16 < 4; k16++) {
            uint32_t bh[8][2], bl[8][2];
#pragma unroll
            for (int nt = 0; nt < 8; nt++) {
                const uint32_t ba = bbase + nt * 8 * RSTRIDE + k16 * 32;
                LDSM_X2(bh[nt], ba);
                LDSM_X2(bl[nt], ba + (OFF_BL - OFF_BH));
            }
#pragma unroll
            for (int mt = 0; mt < 4; mt++) {
                uint32_t ah4[4], al4[4];
                const uint32_t aa = abase + mt * 16 * RSTRIDE + k16 * 32;
                LDSM_X4(ah4, aa);
                LDSM_X4(al4, aa + OFF_AL);
#pragma unroll
                for (int nt = 0; nt < 8; nt++) {
                    MMA16816(acc[mt][nt], ah4, bh[nt][0], bh[nt][1]);
                    MMA16816(acc[mt][nt], ah4, bl[nt][0], bl[nt][1]);
                    MMA16816(acc[mt][nt], al4, bh[nt][0], bh[nt][1]);
                }
            }
        }
        __syncthreads();
        if (c + 2 < NCHUNK) { issue_stage(c + 2); CP_COMMIT(); }
    }

#pragma unroll
    for (int mt = 0; mt < 4; mt++) {
        const int row = m0 + wm + mt * 16 + (lane >> 2);
#pragma unroll
        for (int nt = 0; nt < 8; nt++) {
            const int col = n0 + wn + nt * 8 + (lane & 3) * 2;
            if (SPLITOUT) {
                uint32_t h01, l01, h23, l23;
                split2(acc[mt][nt][0], acc[mt][nt][1], h01, l01);
                split2(acc[mt][nt][2], acc[mt][nt][3], h23, l23);
                *(uint32_t*)(Ch + (size_t)row * N + col) = h01;
                *(uint32_t*)(Cl + (size_t)row * N + col) = l01;
                *(uint32_t*)(Ch + (size_t)(row + 8) * N + col) = h23;
                *(uint32_t*)(Cl + (size_t)(row + 8) * N + col) = l23;
            } else {
                *(float2*)(C + (size_t)row * N + col) =
                    make_float2(acc[mt][nt][0], acc[mt][nt][1]);
                *(float2*)(C + (size_t)(row + 8) * N + col) =
                    make_float2(acc[mt][nt][2], acc[mt][nt][3]);
            }
        }
    }
}

// ---------------------------------------------------------------------------
// HMMA causal flash attention (unchanged from R5).
// ---------------------------------------------------------------------------
#define A_OFF_QH 0
#define A_OFF_QL 18432
#define A_KV0 36864
#define A_KVSTAGE 36864          // Kh(9216) Kl(9216) Vh(9216) Vl(9216)
#define ATT_SMEM (A_KV0 + 3 * A_KVSTAGE)

__global__ void __launch_bounds__(256, 1)
attn_mma(const __nv_bfloat16* __restrict__ qkvh, const __nv_bfloat16* __restrict__ qkvl,
         __nv_bfloat16* __restrict__ Oh, __nv_bfloat16* __restrict__ Ol) {
    extern __shared__ char smem[];
    const uint32_t sb = smem_u32(smem);
    const int tid = threadIdx.x;
    const int warp = tid >> 5, lane = tid & 31;
    const int qt = 7 - blockIdx.x;
    const int b = blockIdx.y >> 4, h = blockIdx.y & 15;
    const int qrow0 = qt * 128;
    const size_t rowbase = (size_t)b * SS;
    const int jlast = 2 * qt + 1;

#pragma unroll
    for (int i = 0; i < 4; i++) {
        const int idx = tid + i * 256;
        const int row = idx >> 3;
        const int c8 = (idx & 7) * 8;
        const size_t g = (rowbase + qrow0 + row) * 3072 + h * DH + c8;
        const uint32_t so = sb + (uint32_t)row * RSTRIDE + (uint32_t)c8 * 2;
        CP_ASYNC16(so + A_OFF_QH, qkvh + g);
        CP_ASYNC16(so + A_OFF_QL, qkvl + g);
    }
    auto issue_kv = [&](int j) {
        const uint32_t so = sb + A_KV0 + (uint32_t)(j % 3) * A_KVSTAGE;
#pragma unroll
        for (int i = 0; i < 2; i++) {
            const int idx = tid + i * 256;
            const int row = idx >> 3;
            const int c8 = (idx & 7) * 8;
            const size_t g = (rowbase + j * 64 + row) * 3072 + h * DH + c8;
            const uint32_t soff = so + (uint32_t)row * RSTRIDE + (uint32_t)c8 * 2;
            CP_ASYNC16(soff,         qkvh + g + 1024);
            CP_ASYNC16(soff + 9216,  qkvl + g + 1024);
            CP_ASYNC16(soff + 18432, qkvh + g + 2048);
            CP_ASYNC16(soff + 27648, qkvl + g + 2048);
        }
    };
    issue_kv(0); CP_COMMIT();
    if (jlast >= 1) { issue_kv(1); CP_COMMIT(); }

    if (jlast >= 1) { CP_WAIT1(); } else { CP_WAIT0(); }
    __syncthreads();

    uint32_t qh[4][4], ql[4][4];
    {
        const uint32_t qbase = sb + (uint32_t)(warp * 16 + (lane & 15)) * RSTRIDE
                             + (uint32_t)(lane >> 4) * 16;
#pragma unroll
        for (int ks = 0; ks < 4; ks++) {
            LDSM_X4(qh[ks], qbase + A_OFF_QH + ks * 32);
            LDSM_X4(ql[ks], qbase + A_OFF_QL + ks * 32);
        }
    }

    float O[8][4];
#pragma unroll
    for (int dt = 0; dt < 8; dt++)
#pragma unroll
        for (int i = 0; i < 4; i++) O[dt][i] = 0.f;
    float m0 = -1e30f, m1 = -1e30f, l0 = 0.f, l1 = 0.f;

    const int rg0 = qrow0 + warp * 16 + (lane >> 2);
    const float SC = 0.18033688011112042f;     // (1/8) * log2(e)

#pragma unroll 1
    for (int j = 0; j <= jlast; j++) {
        if (j + 2 <= jlast) { issue_kv(j + 2); CP_COMMIT(); }
        if (j + 2 <= jlast)      { CP_WAIT2(); }
        else if (j + 1 <= jlast) { CP_WAIT1(); }
        else                     { CP_WAIT0(); }
        __syncthreads();

        const bool active = (64 * j) <= (qrow0 + warp * 16 + 15);
        if (active) {
            const uint32_t so = sb + A_KV0 + (uint32_t)(j % 3) * A_KVSTAGE;

            float S[8][4];
#pragma unroll
            for (int nt = 0; nt < 8; nt++)
#pragma unroll
                for (int i = 0; i < 4; i++) S[nt][i] = 0.f;

            const uint32_t kbase = so + (uint32_t)(lane & 7) * RSTRIDE
                                 + (uint32_t)(lane >> 3) * 16;
#pragma unroll
            for (int nt = 0; nt < 8; nt++) {
                const uint32_t ka = kbase + nt * 8 * RSTRIDE;
                uint32_t kh0[4], kh1[4], kl0[4], kl1[4];
                LDSM_X4(kh0, ka);          LDSM_X4(kh1, ka + 64);
                LDSM_X4(kl0, ka + 9216);   LDSM_X4(kl1, ka + 9216 + 64);
                MMA16816(S[nt], qh[0], kh0[0], kh0[1]);
                MMA16816(S[nt], qh[0], kl0[0], kl0[1]);
                MMA16816(S[nt], ql[0], kh0[0], kh0[1]);
                MMA16816(S[nt], qh[1], kh0[2], kh0[3]);
                MMA16816(S[nt], qh[1], kl0[2], kl0[3]);
                MMA16816(S[nt], ql[1], kh0[2], kh0[3]);
                MMA16816(S[nt], qh[2], kh1[0], kh1[1]);
                MMA16816(S[nt], qh[2], kl1[0], kl1[1]);
                MMA16816(S[nt], ql[2], kh1[0], kh1[1]);
                MMA16816(S[nt], qh[3], kh1[2], kh1[3]);
                MMA16816(S[nt], qh[3], kl1[2], kl1[3]);
                MMA16816(S[nt], ql[3], kh1[2], kh1[3]);
            }

            const bool needmask = (j >= 2 * qt);
            float mx0 = -1e30f, mx1 = -1e30f;
#pragma unroll
            for (int nt = 0; nt < 8; nt++) {
                float t0 = S[nt][0] * SC, t1 = S[nt][1] * SC;
                float t2 = S[nt][2] * SC, t3 = S[nt][3] * SC;
                if (needmask) {
                    const int col = 64 * j + 8 * nt + 2 * (lane & 3);
                    if (col > rg0)         t0 = -1e30f;
                    if (col + 1 > rg0)     t1 = -1e30f;
                    if (col > rg0 + 8)     t2 = -1e30f;
                    if (col + 1 > rg0 + 8) t3 = -1e30f;
                }
                S[nt][0] = t0; S[nt][1] = t1; S[nt][2] = t2; S[nt][3] = t3;
                mx0 = fmaxf(mx0, fmaxf(t0, t1));
                mx1 = fmaxf(mx1, fmaxf(t2, t3));
            }
            mx0 = fmaxf(mx0, __shfl_xor_sync(0xffffffffu, mx0, 1));
            mx0 = fmaxf(mx0, __shfl_xor_sync(0xffffffffu, mx0, 2));
            mx1 = fmaxf(mx1, __shfl_xor_sync(0xffffffffu, mx1, 1));
            mx1 = fmaxf(mx1, __shfl_xor_sync(0xffffffffu, mx1, 2));

            const float mn0 = fmaxf(m0, mx0), mn1 = fmaxf(m1, mx1);
            const float cr0 = ex2(m0 - mn0), cr1 = ex2(m1 - mn1);
            m0 = mn0; m1 = mn1;

            float ls0 = 0.f, ls1 = 0.f;
#pragma unroll
            for (int nt = 0; nt < 8; nt++) {
                const float p0 = ex2(S[nt][0] - m0), p1 = ex2(S[nt][1] - m0);
                const float p2 = ex2(S[nt][2] - m1), p3 = ex2(S[nt][3] - m1);
                S[nt][0] = p0; S[nt][1] = p1; S[nt][2] = p2; S[nt][3] = p3;
                ls0 += p0 + p1;
                ls1 += p2 + p3;
            }
            ls0 += __shfl_xor_sync(0xffffffffu, ls0, 1);
            ls0 += __shfl_xor_sync(0xffffffffu, ls0, 2);
            ls1 += __shfl_xor_sync(0xffffffffu, ls1, 1);
            ls1 += __shfl_xor_sync(0xffffffffu, ls1, 2);
            l0 = l0 * cr0 + ls0;
            l1 = l1 * cr1 + ls1;

#pragma unroll
            for (int dt = 0; dt < 8; dt++) {
                O[dt][0] *= cr0; O[dt][1] *= cr0;
                O[dt][2] *= cr1; O[dt][3] *= cr1;
            }

            uint32_t ph[4][4], pl[4][4];
#pragma unroll
            for (int ks = 0; ks < 4; ks++) {
                split2(S[2 * ks][0],     S[2 * ks][1],     ph[ks][0], pl[ks][0]);
                split2(S[2 * ks][2],     S[2 * ks][3],     ph[ks][1], pl[ks][1]);
                split2(S[2 * ks + 1][0], S[2 * ks + 1][1], ph[ks][2], pl[ks][2]);
                split2(S[2 * ks + 1][2], S[2 * ks + 1][3], ph[ks][3], pl[ks][3]);
            }

            const uint32_t vbase = so + 18432 + (uint32_t)lane * RSTRIDE;
#pragma unroll
            for (int dt = 0; dt < 8; dt++) {
                const uint32_t va = vbase + dt * 16;
                uint32_t vh0[4], vh1[4], vl0[4], vl1[4];
                LDSM_X4_T(vh0, va);                 LDSM_X4_T(vh1, va + 32 * RSTRIDE);
                LDSM_X4_T(vl0, va + 9216);          LDSM_X4_T(vl1, va + 9216 + 32 * RSTRIDE);
                MMA16816(O[dt], ph[0], vh0[0], vh0[1]);
                MMA16816(O[dt], ph[0], vl0[0], vl0[1]);
                MMA16816(O[dt], pl[0], vh0[0], vh0[1]);
                MMA16816(O[dt], ph[1], vh0[2], vh0[3]);
                MMA16816(O[dt], ph[1], vl0[2], vl0[3]);
                MMA16816(O[dt], pl[1], vh0[2], vh0[3]);
                MMA16816(O[dt], ph[2], vh1[0], vh1[1]);
                MMA16816(O[dt], ph[2], vl1[0], vl1[1]);
                MMA16816(O[dt], pl[2], vh1[0], vh1[1]);
                MMA16816(O[dt], ph[3], vh1[2], vh1[3]);
                MMA16816(O[dt], ph[3], vl1[2], vl1[3]);
                MMA16816(O[dt], pl[3], vh1[2], vh1[3]);
            }
        }
        __syncthreads();
    }

    const float inv0 = 1.f / l0, inv1 = 1.f / l1;
    const size_t row0 = rowbase + qrow0 + warp * 16 + (lane >> 2);
    const size_t row1 = row0 + 8;
#pragma unroll
    for (int dt = 0; dt < 8; dt++) {
        const int col = h * DH + dt * 8 + 2 * (lane & 3);
        uint32_t h01, l01, h23, l23;
        split2(O[dt][0] * inv0, O[dt][1] * inv0, h01, l01);
        split2(O[dt][2] * inv1, O[dt][3] * inv1, h23, l23);
        *(uint32_t*)(Oh + row0 * DD + col) = h01;
        *(uint32_t*)(Ol + row0 * DD + col) = l01;
        *(uint32_t*)(Oh + row1 * DD + col) = h23;
        *(uint32_t*)(Ol + row1 * DD + col) = l23;
    }
}

// ---------------------------------------------------------------------------
extern "C" void kernel_launch(void* const* d_in, const int* in_sizes, int n_in,
                              void* d_out, int out_size) {
    const float* x     = (const float*)d_in[0];   // [8,1024,1024]
    const float* w_qkv = (const float*)d_in[2];   // [1024,3072]
    const float* w_out = (const float*)d_in[3];   // [1024,1024]
    float* out = (float*)d_out;

    __nv_bfloat16 *wqh, *wql, *woh, *wol, *ah, *al, *qkvh, *qkvl;
    cudaGetSymbolAddress((void**)&wqh, g_wqkv_h);
    cudaGetSymbolAddress((void**)&wql, g_wqkv_l);
    cudaGetSymbolAddress((void**)&woh, g_wout_h);
    cudaGetSymbolAddress((void**)&wol, g_wout_l);
    cudaGetSymbolAddress((void**)&ah, g_ah);
    cudaGetSymbolAddress((void**)&al, g_al);
    cudaGetSymbolAddress((void**)&qkvh, g_qkvh);
    cudaGetSymbolAddress((void**)&qkvl, g_qkvl);

    cudaFuncSetAttribute(gemm_mma<true>,  cudaFuncAttributeMaxDynamicSharedMemorySize, GEMM_SMEM);
    cudaFuncSetAttribute(gemm_mma<false>, cudaFuncAttributeMaxDynamicSharedMemorySize, GEMM_SMEM);
    cudaFuncSetAttribute(attn_mma, cudaFuncAttributeMaxDynamicSharedMemorySize, ATT_SMEM);

    // 0) weight transpose+split, activation split
    wsplit_kernel<<<dim3(3072 / 32, 1024 / 32), dim3(32, 8)>>>(w_qkv, wqh, wql, 1024, 3072);
    wsplit_kernel<<<dim3(1024 / 32, 1024 / 32), dim3(32, 8)>>>(w_out, woh, wol, 1024, 1024);
    xsplit_kernel<<<(8192 * 1024 / 4) / 256, 256>>>(x, ah, al);

    // 1) QKV projection -> split bf16 qkv
    gemm_mma<true><<<dim3(3072 / 256, 8192 / 128), 256, GEMM_SMEM>>>(
        ah, al, wqh, wql, nullptr, qkvh, qkvl, 3072);

    // 2) causal flash attention (HMMA) -> split bf16 O
    attn_mma<<<dim3(8, BB * HH), 256, ATT_SMEM>>>(qkvh, qkvl, ah, al);

    // 3) output projection -> fp32 out
    gemm_mma<false><<<dim3(1024 / 256, 8192 / 128), 256, GEMM_SMEM>>>(
        ah, al, woh, wol, out, nullptr, nullptr, 1024);
}